// round 11
// baseline (speedup 1.0000x reference)
#include <cuda_runtime.h>
#include <cstdint>

#define BATCH   16
#define NPTS    8192
#define NPOINT  2048
#define KNN     16
#define CIN     64
#define COUT    128
#define CAP     384
#define QPB     8

#define GEMM_BLOCKS 1024
#define KNN_BLOCKS  (BATCH * (NPOINT / QPB))           // 4096
#define GRID        (BATCH + GEMM_BLOCKS + KNN_BLOCKS) // 5136
#define FEAT_OFF    (BATCH * NPOINT * 3)
#define SMEM_BYTES  132096                             // 128KB + 1KB red zone

// ---------------- scratch ----------------
__device__ __align__(16) float g_h[BATCH * NPTS * COUT];
__device__ int      g_fps[BATCH * NPOINT];
__device__ float    g_sum[COUT];
__device__ float    g_sq[COUT];
__device__ __align__(16) float g_scale[COUT];
__device__ __align__(16) float g_shift[COUT];
__device__ unsigned g_prog[BATCH];
__device__ unsigned g_done;
__device__ unsigned g_flag;

__global__ void zero_kernel() {
    int t = threadIdx.x;
    if (t < COUT) { g_sum[t] = 0.f; g_sq[t] = 0.f; }
    if (t < BATCH) g_prog[t] = 0u;
    if (t == 0) { g_done = 0u; g_flag = 0u; }
}

// ---------------- helpers ----------------
typedef unsigned long long ull;
__device__ __forceinline__ ull pk2(float a, float b) {
    ull r; asm("mov.b64 %0,{%1,%2};" : "=l"(r) : "f"(a), "f"(b)); return r;
}
__device__ __forceinline__ void up2(ull v, float& a, float& b) {
    asm("mov.b64 {%0,%1},%2;" : "=f"(a), "=f"(b) : "l"(v));
}
__device__ __forceinline__ void up2u(ull v, unsigned& a, unsigned& b) {
    asm("mov.b64 {%0,%1},%2;" : "=r"(a), "=r"(b) : "l"(v));
}
__device__ __forceinline__ ull add2(ull a, ull b) {
    ull r; asm("add.rn.f32x2 %0,%1,%2;" : "=l"(r) : "l"(a), "l"(b)); return r;
}
__device__ __forceinline__ ull mul2(ull a, ull b) {
    ull r; asm("mul.rn.f32x2 %0,%1,%2;" : "=l"(r) : "l"(a), "l"(b)); return r;
}
__device__ __forceinline__ ull fma2(ull a, ull b, ull c) {
    ull r; asm("fma.rn.f32x2 %0,%1,%2,%3;" : "=l"(r) : "l"(a), "l"(b), "l"(c)); return r;
}
__device__ __forceinline__ void st_rel(unsigned* p, unsigned v) {
    asm volatile("st.release.gpu.u32 [%0],%1;" :: "l"(p), "r"(v) : "memory");
}
__device__ __forceinline__ unsigned ld_acq(const unsigned* p) {
    unsigned v; asm volatile("ld.acquire.gpu.u32 %0,[%1];" : "=r"(v) : "l"(p) : "memory"); return v;
}
__device__ __forceinline__ unsigned expand10(unsigned v) {
    v &= 1023u;
    v = (v | (v << 16)) & 0x030000FFu;
    v = (v | (v << 8))  & 0x0300F00Fu;
    v = (v | (v << 4))  & 0x030C30C3u;
    v = (v | (v << 2))  & 0x09249249u;
    return v;
}

// ---------------- mega kernel ----------------
__global__ __launch_bounds__(512) void mega_kernel(
    const float* __restrict__ xyz,
    const float* __restrict__ feat,
    const float* __restrict__ Wm,
    const float* __restrict__ gamma,
    const float* __restrict__ beta,
    float* __restrict__ out)
{
    extern __shared__ float smem[];
    int tid = threadIdx.x;
    int bix = blockIdx.x;
    int lane = tid & 31, wid = tid >> 5;

    if (bix < BATCH) {
        // ====== FPS: Morton sort + WARP-uniform exact bbox skip + int compares ======
        int b = bix;
        const float* base = xyz + (size_t)b * NPTS * 3;

        float* sx   = smem;                       // [8192]
        float* sy   = smem + NPTS;                // [8192]
        float* sz   = smem + 2 * NPTS;            // [8192]
        int*   sIdx = (int*)(smem + 3 * NPTS);    // [8192]
        ull*   keys = (ull*)smem;                 // aliases sx+sy during sort
        float* rz   = smem + 4 * NPTS;            // red zone @128K
        ull*   wkeys = (ull*)rz;                  // [2][16] = 256B
        float* rbb  = rz + 64;                    // bbox scratch [102]
        int*   rPos0 = (int*)(rz + 170);          // [1]

        if (tid == 0) {
            g_fps[b * NPOINT] = 0;
            st_rel(&g_prog[b], 1u);
        }

        // --- phase A: load coords, block bbox (for Morton scaling) ---
        float arr[48];
        {
            const float4* s4 = (const float4*)base + tid * 12;
            float4 v[12];
#pragma unroll
            for (int i = 0; i < 12; i++) v[i] = s4[i];
#pragma unroll
            for (int i = 0; i < 12; i++) {
                arr[i * 4 + 0] = v[i].x; arr[i * 4 + 1] = v[i].y;
                arr[i * 4 + 2] = v[i].z; arr[i * 4 + 3] = v[i].w;
            }
        }
        {
            float mnx = 1e30f, mny = 1e30f, mnz = 1e30f;
            float mxx = -1e30f, mxy = -1e30f, mxz = -1e30f;
#pragma unroll
            for (int j = 0; j < 16; j++) {
                mnx = fminf(mnx, arr[3 * j]);     mxx = fmaxf(mxx, arr[3 * j]);
                mny = fminf(mny, arr[3 * j + 1]); mxy = fmaxf(mxy, arr[3 * j + 1]);
                mnz = fminf(mnz, arr[3 * j + 2]); mxz = fmaxf(mxz, arr[3 * j + 2]);
            }
#pragma unroll
            for (int off = 16; off; off >>= 1) {
                mnx = fminf(mnx, __shfl_xor_sync(0xffffffffu, mnx, off));
                mny = fminf(mny, __shfl_xor_sync(0xffffffffu, mny, off));
                mnz = fminf(mnz, __shfl_xor_sync(0xffffffffu, mnz, off));
                mxx = fmaxf(mxx, __shfl_xor_sync(0xffffffffu, mxx, off));
                mxy = fmaxf(mxy, __shfl_xor_sync(0xffffffffu, mxy, off));
                mxz = fmaxf(mxz, __shfl_xor_sync(0xffffffffu, mxz, off));
            }
            if (lane == 0) {
                rbb[wid * 6 + 0] = mnx; rbb[wid * 6 + 1] = mny; rbb[wid * 6 + 2] = mnz;
                rbb[wid * 6 + 3] = mxx; rbb[wid * 6 + 4] = mxy; rbb[wid * 6 + 5] = mxz;
            }
        }
        __syncthreads();
        if (tid == 0) {
            float mn[3] = {1e30f, 1e30f, 1e30f}, mx[3] = {-1e30f, -1e30f, -1e30f};
            for (int w = 0; w < 16; w++)
                for (int d = 0; d < 3; d++) {
                    mn[d] = fminf(mn[d], rbb[w * 6 + d]);
                    mx[d] = fmaxf(mx[d], rbb[w * 6 + 3 + d]);
                }
            for (int d = 0; d < 3; d++) {
                rbb[96 + d] = mn[d];
                rbb[99 + d] = 1023.0f / fmaxf(mx[d] - mn[d], 1e-9f);
            }
        }
        __syncthreads();
        // --- phase B: Morton keys ---
        {
            float ox = rbb[96], oy = rbb[97], oz = rbb[98];
            float sxc = rbb[99], syc = rbb[100], szc = rbb[101];
#pragma unroll
            for (int j = 0; j < 16; j++) {
                int p = tid * 16 + j;
                unsigned ux = (unsigned)fminf(fmaxf((arr[3 * j]     - ox) * sxc, 0.f), 1023.f);
                unsigned uy = (unsigned)fminf(fmaxf((arr[3 * j + 1] - oy) * syc, 0.f), 1023.f);
                unsigned uz = (unsigned)fminf(fmaxf((arr[3 * j + 2] - oz) * szc, 0.f), 1023.f);
                unsigned mo = (expand10(ux) << 2) | (expand10(uy) << 1) | expand10(uz);
                keys[p] = ((ull)mo << 13) | (unsigned)p;
            }
        }
        __syncthreads();
        // --- phase C: bitonic sort ---
        for (int kk = 2; kk <= NPTS; kk <<= 1) {
            for (int jj = kk >> 1; jj > 0; jj >>= 1) {
#pragma unroll
                for (int m = 0; m < 8; m++) {
                    int c = m * 512 + tid;
                    int i = ((c & ~(jj - 1)) << 1) | (c & (jj - 1));
                    int ixj = i | jj;
                    ull a = keys[i], bb2 = keys[ixj];
                    bool up = ((i & kk) == 0);
                    if ((a > bb2) == up) { keys[i] = bb2; keys[ixj] = a; }
                }
                __syncthreads();
            }
        }
        // --- phase D: extract original indices ---
        for (int i = tid; i < NPTS; i += 512) {
            int oi = (int)(keys[i] & 0x1FFFu);
            sIdx[i] = oi;
            if (oi == 0) *rPos0 = i;
        }
        __syncthreads();
        // --- phase E: gather coords into sorted order ---
        for (int i = tid; i < NPTS; i += 512) {
            int oi = sIdx[i];
            sx[i] = __ldg(base + oi * 3 + 0);
            sy[i] = __ldg(base + oi * 3 + 1);
            sz[i] = __ldg(base + oi * 3 + 2);
        }
        __syncthreads();

        // --- phase F: packed registers + WARP bbox (lane-uniform) ---
        ull px[8], py[8], pz[8];
        unsigned ub[16];
        float wbxl, wbxh, wbyl, wbyh, wbzl, wbzh;
        {
            float xx[16], yy[16], zz[16];
#pragma unroll
            for (int j = 0; j < 16; j++) {
                int p = tid * 16 + j;
                xx[j] = sx[p]; yy[j] = sy[p]; zz[j] = sz[p];
            }
            float l0 = xx[0], h0 = xx[0], l1 = yy[0], h1 = yy[0], l2 = zz[0], h2 = zz[0];
#pragma unroll
            for (int j = 1; j < 16; j++) {
                l0 = fminf(l0, xx[j]); h0 = fmaxf(h0, xx[j]);
                l1 = fminf(l1, yy[j]); h1 = fmaxf(h1, yy[j]);
                l2 = fminf(l2, zz[j]); h2 = fmaxf(h2, zz[j]);
            }
#pragma unroll
            for (int off = 16; off; off >>= 1) {
                l0 = fminf(l0, __shfl_xor_sync(0xffffffffu, l0, off));
                h0 = fmaxf(h0, __shfl_xor_sync(0xffffffffu, h0, off));
                l1 = fminf(l1, __shfl_xor_sync(0xffffffffu, l1, off));
                h1 = fmaxf(h1, __shfl_xor_sync(0xffffffffu, h1, off));
                l2 = fminf(l2, __shfl_xor_sync(0xffffffffu, l2, off));
                h2 = fmaxf(h2, __shfl_xor_sync(0xffffffffu, h2, off));
            }
            wbxl = l0; wbxh = h0; wbyl = l1; wbyh = h1; wbzl = l2; wbzh = h2;
#pragma unroll
            for (int pr = 0; pr < 8; pr++) {
                px[pr] = pk2(xx[2 * pr], xx[2 * pr + 1]);
                py[pr] = pk2(yy[2 * pr], yy[2 * pr + 1]);
                pz[pr] = pk2(zz[2 * pr], zz[2 * pr + 1]);
            }
        }
#pragma unroll
        for (int j = 0; j < 16; j++) ub[j] = __float_as_uint(1e10f);
        float    wMaxF = 1e10f;
        unsigned wMaxB = __float_as_uint(1e10f);
        unsigned wCand = 0;
        int winnerPos = *rPos0;

        // --- phase G: iterations, warp-uniform exact skip, 1 barrier each ---
        for (int t = 1; t < NPOINT; t++) {
            float cx = sx[winnerPos], cy = sy[winnerPos], cz = sz[winnerPos];
            float dxa = fmaxf(fmaxf(wbxl - cx, cx - wbxh), 0.f);
            float dya = fmaxf(fmaxf(wbyl - cy, cy - wbyh), 0.f);
            float dza = fmaxf(fmaxf(wbzl - cz, cz - wbzh), 0.f);
            float bd2 = fmaf(dxa, dxa, fmaf(dya, dya, dza * dza));
            if (bd2 * 0.999f < wMaxF + 1e-6f) {   // warp-uniform; skip is provably exact
                ull ncx = pk2(-cx, -cx), ncy = pk2(-cy, -cy), ncz = pk2(-cz, -cz);
#pragma unroll
                for (int pr = 0; pr < 8; pr++) {
                    ull dx = add2(px[pr], ncx);
                    ull dy = add2(py[pr], ncy);
                    ull dz = add2(pz[pr], ncz);
                    ull tt = mul2(dz, dz);
                    tt = fma2(dy, dy, tt);
                    tt = fma2(dx, dx, tt);
                    unsigned u0, u1; up2u(tt, u0, u1);
                    ub[2 * pr]     = umin(ub[2 * pr], u0);
                    ub[2 * pr + 1] = umin(ub[2 * pr + 1], u1);
                }
                unsigned m01 = umax(ub[0], ub[1]),  m23 = umax(ub[2], ub[3]);
                unsigned m45 = umax(ub[4], ub[5]),  m67 = umax(ub[6], ub[7]);
                unsigned m89 = umax(ub[8], ub[9]),  mab = umax(ub[10], ub[11]);
                unsigned mcd = umax(ub[12], ub[13]), mef = umax(ub[14], ub[15]);
                unsigned q0_ = umax(umax(m01, m23), umax(m45, m67));
                unsigned q1_ = umax(umax(m89, mab), umax(mcd, mef));
                unsigned lm = umax(q0_, q1_);
                unsigned wm = __reduce_max_sync(0xffffffffu, lm);
                unsigned cand = 0xffffffffu;
                if (lm == wm) {
                    // exact jnp.argmax tie-break: min ORIGINAL index among ties
                    int bo = 0x7fffffff, bp = 0;
#pragma unroll
                    for (int j = 0; j < 16; j++)
                        if (ub[j] == wm) {
                            int oi = sIdx[(tid << 4) + j];
                            if (oi < bo) { bo = oi; bp = (tid << 4) + j; }
                        }
                    cand = ((unsigned)bo << 13) | (unsigned)bp;
                }
                wCand = __reduce_min_sync(0xffffffffu, cand);
                wMaxB = wm;
                wMaxF = __uint_as_float(wm);
            }
            if (lane == 0) wkeys[(t & 1) * 16 + wid] = ((ull)wMaxB << 32) | wCand;
            __syncthreads();
            ull k0 = wkeys[(t & 1) * 16 + (lane & 15)];
            unsigned hi = (unsigned)(k0 >> 32), lo = (unsigned)k0;
            unsigned ghi = __reduce_max_sync(0xffffffffu, hi);
            unsigned cnd2 = (hi == ghi) ? lo : 0xffffffffu;
            unsigned glo = __reduce_min_sync(0xffffffffu, cnd2);
            winnerPos = (int)(glo & 0x1FFFu);
            if (tid == 0) {
                g_fps[b * NPOINT + t] = (int)(glo >> 13);
                if ((t & 7) == 7) st_rel(&g_prog[b], (unsigned)(t + 1));
            }
        }
    } else if (bix < BATCH + GEMM_BLOCKS) {
        // ================= GEMM h = feat @ W^T + BN stats =================
        int bid  = bix - BATCH;
        int row0 = bid * 128;
        float* sf   = smem;                    // [128][65]
        float* sw   = smem + 128 * 65;         // [128][65]
        float* sSum = smem + 2 * 128 * 65;     // [128]
        float* sSq  = sSum + 128;              // [128]
        int*   sLast = (int*)(sSq + 128);      // [1]
        if (tid < 128) { sSum[tid] = 0.f; sSq[tid] = 0.f; }
        const float* fsrc = feat + (size_t)row0 * CIN;
#pragma unroll
        for (int it = 0; it < 16; it++) {
            int e = it * 512 + tid;
            sf[(e >> 6) * 65 + (e & 63)] = fsrc[e];
            sw[(e >> 6) * 65 + (e & 63)] = Wm[e];
        }
        __syncthreads();
        int tx = tid & 31, ty = tid >> 5;
        float acc[8][4];
#pragma unroll
        for (int i = 0; i < 8; i++)
#pragma unroll
            for (int j = 0; j < 4; j++) acc[i][j] = 0.f;
#pragma unroll 8
        for (int k = 0; k < 64; k++) {
            float fr[8], wc[4];
#pragma unroll
            for (int i = 0; i < 8; i++) fr[i] = sf[(ty * 8 + i) * 65 + k];
#pragma unroll
            for (int j = 0; j < 4; j++) wc[j] = sw[(tx + 32 * j) * 65 + k];
#pragma unroll
            for (int i = 0; i < 8; i++)
#pragma unroll
                for (int j = 0; j < 4; j++)
                    acc[i][j] = fmaf(fr[i], wc[j], acc[i][j]);
        }
#pragma unroll
        for (int j = 0; j < 4; j++) {
            int c = tx + 32 * j;
            float s = 0.f, q = 0.f;
#pragma unroll
            for (int i = 0; i < 8; i++) {
                float v = acc[i][j];
                g_h[(size_t)(row0 + ty * 8 + i) * COUT + c] = v;
                s += v;
                q = fmaf(v, v, q);
            }
            atomicAdd(&sSum[c], s);
            atomicAdd(&sSq[c], q);
        }
        __syncthreads();
        if (tid < 128) {
            atomicAdd(&g_sum[tid], sSum[tid]);
            atomicAdd(&g_sq[tid],  sSq[tid]);
        }
        __syncthreads();
        if (tid == 0) {
            __threadfence();
            unsigned o = atomicAdd(&g_done, 1u);
            *sLast = (o == GEMM_BLOCKS - 1) ? 1 : 0;
        }
        __syncthreads();
        if (*sLast) {
            if (tid < COUT) {
                __threadfence();
                int c = tid;
                float inv  = 1.f / (float)(BATCH * NPTS);
                float mean = g_sum[c] * inv;
                float var  = g_sq[c] * inv - mean * mean;
                float sc   = gamma[c] * rsqrtf(var + 1e-5f);
                g_scale[c] = sc;
                g_shift[c] = beta[c] - mean * sc;
            }
            __syncthreads();
            if (tid == 0) { __threadfence(); st_rel(&g_flag, 1u); }
        }
    } else {
        // ================= kNN + max-pool: 8 queries/block =================
        int kb   = bix - BATCH - GEMM_BLOCKS;
        int b    = kb & 15;
        int qblk = kb >> 4;
        int q0   = qblk * QPB;
        const float* base = xyz + (size_t)b * NPTS * 3;

        int*      hist  = (int*)smem;                         // [1024]
        unsigned* candB = (unsigned*)(smem + 1024);           // [8][CAP]
        int*      candI = (int*)(smem + 1024 + 8 * CAP);      // [8][CAP]
        float*    sDist = smem + 1024 + 16 * CAP;             // [8192] fallback
        float4*   sPool = (float4*)(smem + 1024 + 16 * CAP + NPTS); // [8][32]
        float*    tail  = smem + 1024 + 16 * CAP + NPTS + 1024;
        float*    sQ    = tail;                 // [24]
        int*      nbr   = (int*)(tail + 24);    // [128]
        int*      cnt   = (int*)(tail + 152);   // [8]
        int*      ovf   = (int*)(tail + 160);   // [8]
        int*      sBin  = (int*)(tail + 168);   // [8]
        int*      sFid  = (int*)(tail + 176);   // [8]
        ull*      sKey  = (ull*)(tail + 184);   // [1]

        float arr[48];
        {
            const float4* s4 = (const float4*)base + tid * 12;
            float4 v[12];
#pragma unroll
            for (int i = 0; i < 12; i++) v[i] = s4[i];
#pragma unroll
            for (int i = 0; i < 12; i++) {
                arr[i * 4 + 0] = v[i].x; arr[i * 4 + 1] = v[i].y;
                arr[i * 4 + 2] = v[i].z; arr[i * 4 + 3] = v[i].w;
            }
        }
        ull px[8], py[8], pz[8];
#pragma unroll
        for (int pr = 0; pr < 8; pr++) {
            px[pr] = pk2(arr[(2 * pr) * 3 + 0], arr[(2 * pr + 1) * 3 + 0]);
            py[pr] = pk2(arr[(2 * pr) * 3 + 1], arr[(2 * pr + 1) * 3 + 1]);
            pz[pr] = pk2(arr[(2 * pr) * 3 + 2], arr[(2 * pr + 1) * 3 + 2]);
        }

        if (tid < 8) { cnt[tid] = 0; ovf[tid] = 0; }
        if (tid == 0) {
            unsigned need = (unsigned)(q0 + QPB);
            while (ld_acq(&g_prog[b]) < need) __nanosleep(200);
            for (int q = 0; q < QPB; q++) sFid[q] = g_fps[b * NPOINT + q0 + q];
        }
        __syncthreads();
        if (tid < 24) {
            int q = tid / 3, d = tid % 3;
            float vv = __ldg(base + sFid[q] * 3 + d);
            sQ[q * 3 + d] = vv;
            out[(size_t)(b * NPOINT + q0 + q) * 3 + d] = vv;
        }

        float dq[16];
        for (int q = 0; q < QPB; q++) {
            for (int i = tid; i < 1024; i += 512) hist[i] = 0;
            __syncthreads();
            float cxq = sQ[3 * q], cyq = sQ[3 * q + 1], czq = sQ[3 * q + 2];
            ull ncx = pk2(-cxq, -cxq), ncy = pk2(-cyq, -cyq), ncz = pk2(-czq, -czq);
#pragma unroll
            for (int pr = 0; pr < 8; pr++) {
                ull dx = add2(px[pr], ncx);
                ull dy = add2(py[pr], ncy);
                ull dz = add2(pz[pr], ncz);
                ull tt = mul2(dz, dz);
                tt = fma2(dy, dy, tt);
                tt = fma2(dx, dx, tt);
                up2(tt, dq[2 * pr], dq[2 * pr + 1]);
            }
            atomicAdd(&hist[__float_as_uint(dq[0]) >> 21], 1);
            atomicAdd(&hist[__float_as_uint(dq[8]) >> 21], 1);
            __syncthreads();
            if (wid == 0) {
                int cum = 0, found = -1;
                for (int ch = 0; ch < 32 && found < 0; ch++) {
                    int v = hist[ch * 32 + lane];
                    int s = v;
#pragma unroll
                    for (int off = 1; off < 32; off <<= 1) {
                        int o = __shfl_up_sync(0xffffffffu, s, off);
                        if (lane >= off) s += o;
                    }
                    int tot = __shfl_sync(0xffffffffu, s, 31);
                    unsigned m = __ballot_sync(0xffffffffu, cum + s >= KNN);
                    if (m) found = ch * 32 + __ffs(m) - 1;
                    cum += tot;
                }
                if (lane == 0) sBin[q] = found;
            }
            __syncthreads();
            int bs = sBin[q];
#pragma unroll
            for (int j = 0; j < 16; j++) {
                unsigned bits = __float_as_uint(dq[j]);
                if ((int)(bits >> 21) <= bs) {
                    int pos = atomicAdd(&cnt[q], 1);
                    if (pos < CAP) {
                        candB[q * CAP + pos] = bits;
                        candI[q * CAP + pos] = (tid << 4) + j;
                    } else ovf[q] = 1;
                }
            }
        }
        __syncthreads();

        if (wid < QPB) {
            int q = wid;
            if (!ovf[q]) {
                int C = cnt[q]; if (C > CAP) C = CAP;
                unsigned* cb = candB + q * CAP;
                int* ci_ = candI + q * CAP;
                for (int k = 0; k < KNN; k++) {
                    unsigned mb = 0xFFFFFFFFu; int mi = 0x7fffffff, ms = -1;
                    for (int s = lane; s < C; s += 32) {
                        unsigned bb = cb[s];
                        if (bb < mb) { mb = bb; mi = ci_[s]; ms = s; }
                        else if (bb == mb) { int ii = ci_[s]; if (ii < mi) { mi = ii; ms = s; } }
                    }
                    unsigned g  = __reduce_min_sync(0xffffffffu, mb);
                    unsigned cc = (mb == g) ? (unsigned)mi : 0xffffffffu;
                    unsigned gi = __reduce_min_sync(0xffffffffu, cc);
                    if (mb == g && (unsigned)mi == gi) cb[ms] = 0xFFFFFFFFu;
                    if (lane == 0) nbr[q * KNN + k] = (int)gi;
                    __syncwarp();
                }
            }
        }
        __syncthreads();

        for (int q = 0; q < QPB; q++) {
            if (!ovf[q]) continue;
            float cxq = sQ[3 * q], cyq = sQ[3 * q + 1], czq = sQ[3 * q + 2];
            ull ncx = pk2(-cxq, -cxq), ncy = pk2(-cyq, -cyq), ncz = pk2(-czq, -czq);
#pragma unroll
            for (int pr = 0; pr < 8; pr++) {
                ull dx = add2(px[pr], ncx);
                ull dy = add2(py[pr], ncy);
                ull dz = add2(pz[pr], ncz);
                ull tt = mul2(dz, dz);
                tt = fma2(dy, dy, tt);
                tt = fma2(dx, dx, tt);
                float d0, d1; up2(tt, d0, d1);
                sDist[(tid << 4) + 2 * pr] = d0;
                sDist[(tid << 4) + 2 * pr + 1] = d1;
            }
            __syncthreads();
            for (int k = 0; k < KNN; k++) {
                if (tid == 0) *sKey = ~0ull;
                __syncthreads();
                ull best = ~0ull;
#pragma unroll
                for (int j = 0; j < 16; j++) {
                    int p = (tid << 4) + j;
                    ull kk = ((ull)__float_as_uint(sDist[p]) << 32) | (unsigned)p;
                    if (kk < best) best = kk;
                }
                atomicMin(sKey, best);
                __syncthreads();
                int g = (int)(*sKey & 0xffffffffu);
                if (tid == 0) nbr[q * KNN + k] = g;
                if ((g >> 4) == tid) sDist[g] = __uint_as_float(0x7f000000u);
                __syncthreads();
            }
        }

        if (tid == 0) { while (ld_acq(&g_flag) == 0u) __nanosleep(200); }
        __syncthreads();

        {
            int q  = tid >> 6;
            int c4 = tid & 31;
            int rh = (tid >> 5) & 1;
            const float4* hb4 = (const float4*)g_h + (size_t)b * NPTS * 32;
            float4 sc = ((const float4*)g_scale)[c4];
            float4 sh = ((const float4*)g_shift)[c4];
            float4 m = make_float4(-1e30f, -1e30f, -1e30f, -1e30f);
#pragma unroll
            for (int i = 0; i < 8; i++) {
                int r = nbr[q * KNN + rh * 8 + i];
                float4 v = __ldg(&hb4[(size_t)r * 32 + c4]);
                m.x = fmaxf(m.x, fmaf(v.x, sc.x, sh.x));
                m.y = fmaxf(m.y, fmaf(v.y, sc.y, sh.y));
                m.z = fmaxf(m.z, fmaf(v.z, sc.z, sh.z));
                m.w = fmaxf(m.w, fmaf(v.w, sc.w, sh.w));
            }
            if (rh == 1) sPool[q * 32 + c4] = m;
            __syncthreads();
            if (rh == 0) {
                float4 o = sPool[q * 32 + c4];
                m.x = fmaxf(fmaxf(m.x, o.x), 0.f);
                m.y = fmaxf(fmaxf(m.y, o.y), 0.f);
                m.z = fmaxf(fmaxf(m.z, o.z), 0.f);
                m.w = fmaxf(fmaxf(m.w, o.w), 0.f);
                float4* out4 = (float4*)(out + FEAT_OFF);
                out4[(size_t)(b * NPOINT + q0 + q) * 32 + c4] = m;
            }
        }
    }
}

// ---------------- launch ----------------
extern "C" void kernel_launch(void* const* d_in, const int* in_sizes, int n_in,
                              void* d_out, int out_size)
{
    const float* xyz   = (const float*)d_in[0];
    const float* feat  = (const float*)d_in[1];
    const float* Wm    = (const float*)d_in[2];
    // d_in[3] = bias: cancels inside BatchNorm -> unused
    const float* gamma = (const float*)d_in[4];
    const float* beta  = (const float*)d_in[5];
    float* out = (float*)d_out;

    cudaFuncSetAttribute(mega_kernel, cudaFuncAttributeMaxDynamicSharedMemorySize, SMEM_BYTES);
    zero_kernel<<<1, 128>>>();
    mega_kernel<<<GRID, 512, SMEM_BYTES>>>(xyz, feat, Wm, gamma, beta, out);
}

// round 12
// speedup vs baseline: 2.1930x; 2.1930x over previous
#include <cuda_runtime.h>
#include <cstdint>

#define BATCH   16
#define NPTS    8192
#define NPOINT  2048
#define KNN     16
#define CIN     64
#define COUT    128
#define CAP     384
#define QPB     8
#define NT      1024

#define GEMM_BLOCKS 1024
#define KNN_BLOCKS  (BATCH * (NPOINT / QPB))           // 4096
#define GRID        (BATCH + GEMM_BLOCKS + KNN_BLOCKS) // 5136
#define FEAT_OFF    (BATCH * NPOINT * 3)
#define SMEM_BYTES  (3 * NPTS * 4 + 1024)              // 99328

// ---------------- scratch ----------------
__device__ __align__(16) float g_h[BATCH * NPTS * COUT];
__device__ int      g_fps[BATCH * NPOINT];
__device__ float    g_sum[COUT];
__device__ float    g_sq[COUT];
__device__ __align__(16) float g_scale[COUT];
__device__ __align__(16) float g_shift[COUT];
__device__ unsigned g_prog[BATCH];
__device__ unsigned g_done;
__device__ unsigned g_flag;

__global__ void zero_kernel() {
    int t = threadIdx.x;
    if (t < COUT) { g_sum[t] = 0.f; g_sq[t] = 0.f; }
    if (t < BATCH) g_prog[t] = 0u;
    if (t == 0) { g_done = 0u; g_flag = 0u; }
}

// ---------------- helpers ----------------
typedef unsigned long long ull;
__device__ __forceinline__ ull pk2(float a, float b) {
    ull r; asm("mov.b64 %0,{%1,%2};" : "=l"(r) : "f"(a), "f"(b)); return r;
}
__device__ __forceinline__ void up2(ull v, float& a, float& b) {
    asm("mov.b64 {%0,%1},%2;" : "=f"(a), "=f"(b) : "l"(v));
}
__device__ __forceinline__ void up2u(ull v, unsigned& a, unsigned& b) {
    asm("mov.b64 {%0,%1},%2;" : "=r"(a), "=r"(b) : "l"(v));
}
__device__ __forceinline__ ull add2(ull a, ull b) {
    ull r; asm("add.rn.f32x2 %0,%1,%2;" : "=l"(r) : "l"(a), "l"(b)); return r;
}
__device__ __forceinline__ ull mul2(ull a, ull b) {
    ull r; asm("mul.rn.f32x2 %0,%1,%2;" : "=l"(r) : "l"(a), "l"(b)); return r;
}
__device__ __forceinline__ ull fma2(ull a, ull b, ull c) {
    ull r; asm("fma.rn.f32x2 %0,%1,%2,%3;" : "=l"(r) : "l"(a), "l"(b), "l"(c)); return r;
}
__device__ __forceinline__ void st_rel(unsigned* p, unsigned v) {
    asm volatile("st.release.gpu.u32 [%0],%1;" :: "l"(p), "r"(v) : "memory");
}
__device__ __forceinline__ unsigned ld_acq(const unsigned* p) {
    unsigned v; asm volatile("ld.acquire.gpu.u32 %0,[%1];" : "=r"(v) : "l"(p) : "memory"); return v;
}

// ---------------- mega kernel ----------------
__global__ __launch_bounds__(NT) void mega_kernel(
    const float* __restrict__ xyz,
    const float* __restrict__ feat,
    const float* __restrict__ Wm,
    const float* __restrict__ gamma,
    const float* __restrict__ beta,
    float* __restrict__ out)
{
    extern __shared__ float smem[];
    int tid = threadIdx.x;
    int bix = blockIdx.x;
    int lane = tid & 31, wid = tid >> 5;

    if (bix < BATCH) {
        // ========== FPS: 32 warps, 8 pts/thread, int compares, 1 barrier/iter ==========
        int b = bix;
        const float* base = xyz + (size_t)b * NPTS * 3;

        float* sx    = smem;                      // [8192]
        float* sy    = smem + NPTS;               // [8192]
        float* sz    = smem + 2 * NPTS;           // [8192]
        ull*   wkeys = (ull*)(smem + 3 * NPTS);   // [2][32]

        // load 8 points/thread (24 floats = 6 float4), stage SoA, pack registers
        float arr[24];
        {
            const float4* s4 = (const float4*)base + tid * 6;
            float4 v[6];
#pragma unroll
            for (int i = 0; i < 6; i++) v[i] = s4[i];
#pragma unroll
            for (int i = 0; i < 6; i++) {
                arr[i * 4 + 0] = v[i].x; arr[i * 4 + 1] = v[i].y;
                arr[i * 4 + 2] = v[i].z; arr[i * 4 + 3] = v[i].w;
            }
        }
#pragma unroll
        for (int j = 0; j < 8; j++) {
            int p = tid * 8 + j;
            sx[p] = arr[3 * j + 0];
            sy[p] = arr[3 * j + 1];
            sz[p] = arr[3 * j + 2];
        }
        ull px[4], py[4], pz[4];
        unsigned ub[8];
#pragma unroll
        for (int pr = 0; pr < 4; pr++) {
            px[pr] = pk2(arr[(2 * pr) * 3 + 0], arr[(2 * pr + 1) * 3 + 0]);
            py[pr] = pk2(arr[(2 * pr) * 3 + 1], arr[(2 * pr + 1) * 3 + 1]);
            pz[pr] = pk2(arr[(2 * pr) * 3 + 2], arr[(2 * pr + 1) * 3 + 2]);
        }
#pragma unroll
        for (int j = 0; j < 8; j++) ub[j] = __float_as_uint(1e10f);

        if (tid == 0) {
            g_fps[b * NPOINT] = 0;
            st_rel(&g_prog[b], 1u);
        }
        __syncthreads();
        int winnerPos = 0;

        for (int t = 1; t < NPOINT; t++) {
            float cx = sx[winnerPos], cy = sy[winnerPos], cz = sz[winnerPos];
            ull ncx = pk2(-cx, -cx), ncy = pk2(-cy, -cy), ncz = pk2(-cz, -cz);
#pragma unroll
            for (int pr = 0; pr < 4; pr++) {
                ull dx = add2(px[pr], ncx);
                ull dy = add2(py[pr], ncy);
                ull dz = add2(pz[pr], ncz);
                ull tt = mul2(dz, dz);
                tt = fma2(dy, dy, tt);
                tt = fma2(dx, dx, tt);
                unsigned u0, u1; up2u(tt, u0, u1);
                ub[2 * pr]     = umin(ub[2 * pr], u0);
                ub[2 * pr + 1] = umin(ub[2 * pr + 1], u1);
            }
            // integer max-tree on bits (exact for d >= 0)
            unsigned m01 = umax(ub[0], ub[1]), m23 = umax(ub[2], ub[3]);
            unsigned m45 = umax(ub[4], ub[5]), m67 = umax(ub[6], ub[7]);
            unsigned lm = umax(umax(m01, m23), umax(m45, m67));
            unsigned wm = __reduce_max_sync(0xffffffffu, lm);
            unsigned cand = 0xffffffffu;
            if (lm == wm) {
                int bp = 0x7fffffff;
#pragma unroll
                for (int j = 7; j >= 0; j--)
                    if (ub[j] == wm) bp = (tid << 3) + j;   // smallest index wins
                cand = (unsigned)bp;
            }
            unsigned wc = __reduce_min_sync(0xffffffffu, cand);
            if (lane == 0) wkeys[(t & 1) * 32 + wid] = ((ull)wm << 32) | wc;
            __syncthreads();
            ull k0 = wkeys[(t & 1) * 32 + lane];             // one key per lane, 32 warps
            unsigned hi = (unsigned)(k0 >> 32), lo = (unsigned)k0;
            unsigned ghi = __reduce_max_sync(0xffffffffu, hi);
            unsigned cnd2 = (hi == ghi) ? lo : 0xffffffffu;
            unsigned glo = __reduce_min_sync(0xffffffffu, cnd2);
            winnerPos = (int)glo;
            if (tid == 0) {
                g_fps[b * NPOINT + t] = (int)glo;
                if ((t & 7) == 7) st_rel(&g_prog[b], (unsigned)(t + 1));
            }
        }
    } else if (bix < BATCH + GEMM_BLOCKS) {
        // ========== GEMM h = feat @ W^T + BN stats (1024 threads) ==========
        int bid  = bix - BATCH;
        int row0 = bid * 128;
        float* sf   = smem;                    // [128][65]
        float* sw   = smem + 128 * 65;         // [128][65]
        float* sSum = smem + 2 * 128 * 65;     // [128]
        float* sSq  = sSum + 128;              // [128]
        int*   sLast = (int*)(sSq + 128);      // [1]
        if (tid < 128) { sSum[tid] = 0.f; sSq[tid] = 0.f; }
        const float* fsrc = feat + (size_t)row0 * CIN;
#pragma unroll
        for (int it = 0; it < 8; it++) {
            int e = it * NT + tid;
            sf[(e >> 6) * 65 + (e & 63)] = fsrc[e];
            sw[(e >> 6) * 65 + (e & 63)] = Wm[e];
        }
        __syncthreads();
        int tx = tid & 31, ty = tid >> 5;      // ty: 0..31 -> 4 rows each
        float acc[4][4];
#pragma unroll
        for (int i = 0; i < 4; i++)
#pragma unroll
            for (int j = 0; j < 4; j++) acc[i][j] = 0.f;
#pragma unroll 8
        for (int k = 0; k < 64; k++) {
            float fr[4], wc[4];
#pragma unroll
            for (int i = 0; i < 4; i++) fr[i] = sf[(ty * 4 + i) * 65 + k];
#pragma unroll
            for (int j = 0; j < 4; j++) wc[j] = sw[(tx + 32 * j) * 65 + k];
#pragma unroll
            for (int i = 0; i < 4; i++)
#pragma unroll
                for (int j = 0; j < 4; j++)
                    acc[i][j] = fmaf(fr[i], wc[j], acc[i][j]);
        }
#pragma unroll
        for (int j = 0; j < 4; j++) {
            int c = tx + 32 * j;
            float s = 0.f, q = 0.f;
#pragma unroll
            for (int i = 0; i < 4; i++) {
                float v = acc[i][j];
                g_h[(size_t)(row0 + ty * 4 + i) * COUT + c] = v;
                s += v;
                q = fmaf(v, v, q);
            }
            atomicAdd(&sSum[c], s);
            atomicAdd(&sSq[c], q);
        }
        __syncthreads();
        if (tid < 128) {
            atomicAdd(&g_sum[tid], sSum[tid]);
            atomicAdd(&g_sq[tid],  sSq[tid]);
        }
        __syncthreads();
        if (tid == 0) {
            __threadfence();
            unsigned o = atomicAdd(&g_done, 1u);
            *sLast = (o == GEMM_BLOCKS - 1) ? 1 : 0;
        }
        __syncthreads();
        if (*sLast) {
            if (tid < COUT) {
                __threadfence();
                int c = tid;
                float inv  = 1.f / (float)(BATCH * NPTS);
                float mean = g_sum[c] * inv;
                float var  = g_sq[c] * inv - mean * mean;
                float sc   = gamma[c] * rsqrtf(var + 1e-5f);
                g_scale[c] = sc;
                g_shift[c] = beta[c] - mean * sc;
            }
            __syncthreads();
            if (tid == 0) { __threadfence(); st_rel(&g_flag, 1u); }
        }
    } else {
        // ========== kNN + max-pool: 8 queries/block, 8 pts/thread ==========
        int kb   = bix - BATCH - GEMM_BLOCKS;
        int b    = kb & 15;
        int qblk = kb >> 4;
        int q0   = qblk * QPB;
        const float* base = xyz + (size_t)b * NPTS * 3;

        int*      hist  = (int*)smem;                         // [1024]
        unsigned* candB = (unsigned*)(smem + 1024);           // [8][CAP]
        int*      candI = (int*)(smem + 1024 + 8 * CAP);      // [8][CAP]
        float*    sDist = smem + 1024 + 16 * CAP;             // [8192] fallback
        float4*   sPool = (float4*)(smem + 1024 + 16 * CAP + NPTS); // [8][32]
        float*    tail  = smem + 1024 + 16 * CAP + NPTS + 1024;
        float*    sQ    = tail;                 // [24]
        int*      nbr   = (int*)(tail + 24);    // [128]
        int*      cnt   = (int*)(tail + 152);   // [8]
        int*      ovf   = (int*)(tail + 160);   // [8]
        int*      sBin  = (int*)(tail + 168);   // [8]
        int*      sFid  = (int*)(tail + 176);   // [8]
        ull*      sKey  = (ull*)(tail + 184);   // [1]

        float arr[24];
        {
            const float4* s4 = (const float4*)base + tid * 6;
            float4 v[6];
#pragma unroll
            for (int i = 0; i < 6; i++) v[i] = s4[i];
#pragma unroll
            for (int i = 0; i < 6; i++) {
                arr[i * 4 + 0] = v[i].x; arr[i * 4 + 1] = v[i].y;
                arr[i * 4 + 2] = v[i].z; arr[i * 4 + 3] = v[i].w;
            }
        }
        ull px[4], py[4], pz[4];
#pragma unroll
        for (int pr = 0; pr < 4; pr++) {
            px[pr] = pk2(arr[(2 * pr) * 3 + 0], arr[(2 * pr + 1) * 3 + 0]);
            py[pr] = pk2(arr[(2 * pr) * 3 + 1], arr[(2 * pr + 1) * 3 + 1]);
            pz[pr] = pk2(arr[(2 * pr) * 3 + 2], arr[(2 * pr + 1) * 3 + 2]);
        }

        if (tid < 8) { cnt[tid] = 0; ovf[tid] = 0; }
        if (tid == 0) {
            unsigned need = (unsigned)(q0 + QPB);
            while (ld_acq(&g_prog[b]) < need) __nanosleep(200);
            for (int q = 0; q < QPB; q++) sFid[q] = g_fps[b * NPOINT + q0 + q];
        }
        __syncthreads();
        if (tid < 24) {
            int q = tid / 3, d = tid % 3;
            float vv = __ldg(base + sFid[q] * 3 + d);
            sQ[q * 3 + d] = vv;
            out[(size_t)(b * NPOINT + q0 + q) * 3 + d] = vv;
        }

        float dq[8];
        for (int q = 0; q < QPB; q++) {
            if (tid < 1024) hist[tid] = 0;
            __syncthreads();
            float cxq = sQ[3 * q], cyq = sQ[3 * q + 1], czq = sQ[3 * q + 2];
            ull ncx = pk2(-cxq, -cxq), ncy = pk2(-cyq, -cyq), ncz = pk2(-czq, -czq);
#pragma unroll
            for (int pr = 0; pr < 4; pr++) {
                ull dx = add2(px[pr], ncx);
                ull dy = add2(py[pr], ncy);
                ull dz = add2(pz[pr], ncz);
                ull tt = mul2(dz, dz);
                tt = fma2(dy, dy, tt);
                tt = fma2(dx, dx, tt);
                up2(tt, dq[2 * pr], dq[2 * pr + 1]);
            }
            atomicAdd(&hist[__float_as_uint(dq[0]) >> 21], 1);
            atomicAdd(&hist[__float_as_uint(dq[4]) >> 21], 1);
            __syncthreads();
            if (wid == 0) {   // bin of 16th-smallest among 2048 subsamples (exact bound)
                int cum = 0, found = -1;
                for (int ch = 0; ch < 32 && found < 0; ch++) {
                    int v = hist[ch * 32 + lane];
                    int s = v;
#pragma unroll
                    for (int off = 1; off < 32; off <<= 1) {
                        int o = __shfl_up_sync(0xffffffffu, s, off);
                        if (lane >= off) s += o;
                    }
                    int tot = __shfl_sync(0xffffffffu, s, 31);
                    unsigned m = __ballot_sync(0xffffffffu, cum + s >= KNN);
                    if (m) found = ch * 32 + __ffs(m) - 1;
                    cum += tot;
                }
                if (lane == 0) sBin[q] = found;
            }
            __syncthreads();
            int bs = sBin[q];
#pragma unroll
            for (int j = 0; j < 8; j++) {
                unsigned bits = __float_as_uint(dq[j]);
                if ((int)(bits >> 21) <= bs) {
                    int pos = atomicAdd(&cnt[q], 1);
                    if (pos < CAP) {
                        candB[q * CAP + pos] = bits;
                        candI[q * CAP + pos] = (tid << 3) + j;
                    } else ovf[q] = 1;
                }
            }
        }
        __syncthreads();

        if (wid < QPB) {
            int q = wid;
            if (!ovf[q]) {
                int C = cnt[q]; if (C > CAP) C = CAP;
                unsigned* cb = candB + q * CAP;
                int* ci_ = candI + q * CAP;
                for (int k = 0; k < KNN; k++) {
                    unsigned mb = 0xFFFFFFFFu; int mi = 0x7fffffff, ms = -1;
                    for (int s = lane; s < C; s += 32) {
                        unsigned bb = cb[s];
                        if (bb < mb) { mb = bb; mi = ci_[s]; ms = s; }
                        else if (bb == mb) { int ii = ci_[s]; if (ii < mi) { mi = ii; ms = s; } }
                    }
                    unsigned g  = __reduce_min_sync(0xffffffffu, mb);
                    unsigned cc = (mb == g) ? (unsigned)mi : 0xffffffffu;
                    unsigned gi = __reduce_min_sync(0xffffffffu, cc);
                    if (mb == g && (unsigned)mi == gi) cb[ms] = 0xFFFFFFFFu;
                    if (lane == 0) nbr[q * KNN + k] = (int)gi;
                    __syncwarp();
                }
            }
        }
        __syncthreads();

        // rare fallback: exact block-wide selection with recomputed distances
        for (int q = 0; q < QPB; q++) {
            if (!ovf[q]) continue;
            float cxq = sQ[3 * q], cyq = sQ[3 * q + 1], czq = sQ[3 * q + 2];
            ull ncx = pk2(-cxq, -cxq), ncy = pk2(-cyq, -cyq), ncz = pk2(-czq, -czq);
#pragma unroll
            for (int pr = 0; pr < 4; pr++) {
                ull dx = add2(px[pr], ncx);
                ull dy = add2(py[pr], ncy);
                ull dz = add2(pz[pr], ncz);
                ull tt = mul2(dz, dz);
                tt = fma2(dy, dy, tt);
                tt = fma2(dx, dx, tt);
                float d0, d1; up2(tt, d0, d1);
                sDist[(tid << 3) + 2 * pr] = d0;
                sDist[(tid << 3) + 2 * pr + 1] = d1;
            }
            __syncthreads();
            for (int k = 0; k < KNN; k++) {
                if (tid == 0) *sKey = ~0ull;
                __syncthreads();
                ull best = ~0ull;
#pragma unroll
                for (int j = 0; j < 8; j++) {
                    int p = (tid << 3) + j;
                    ull kk = ((ull)__float_as_uint(sDist[p]) << 32) | (unsigned)p;
                    if (kk < best) best = kk;
                }
                atomicMin(sKey, best);
                __syncthreads();
                int g = (int)(*sKey & 0xffffffffu);
                if (tid == 0) nbr[q * KNN + k] = g;
                if ((g >> 3) == tid) sDist[g] = __uint_as_float(0x7f000000u);
                __syncthreads();
            }
        }

        if (tid == 0) { while (ld_acq(&g_flag) == 0u) __nanosleep(200); }
        __syncthreads();

        // max-pool (threads < 512 do the work; barrier outside the guard)
        {
            int q  = (tid >> 6) & 7;
            int c4 = tid & 31;
            int rh = (tid >> 5) & 1;
            float4 m = make_float4(-1e30f, -1e30f, -1e30f, -1e30f);
            if (tid < 512) {
                const float4* hb4 = (const float4*)g_h + (size_t)b * NPTS * 32;
                float4 sc = ((const float4*)g_scale)[c4];
                float4 sh = ((const float4*)g_shift)[c4];
#pragma unroll
                for (int i = 0; i < 8; i++) {
                    int r = nbr[q * KNN + rh * 8 + i];
                    float4 v = __ldg(&hb4[(size_t)r * 32 + c4]);
                    m.x = fmaxf(m.x, fmaf(v.x, sc.x, sh.x));
                    m.y = fmaxf(m.y, fmaf(v.y, sc.y, sh.y));
                    m.z = fmaxf(m.z, fmaf(v.z, sc.z, sh.z));
                    m.w = fmaxf(m.w, fmaf(v.w, sc.w, sh.w));
                }
                if (rh == 1) sPool[q * 32 + c4] = m;
            }
            __syncthreads();
            if (tid < 512 && rh == 0) {
                float4 o = sPool[q * 32 + c4];
                m.x = fmaxf(fmaxf(m.x, o.x), 0.f);
                m.y = fmaxf(fmaxf(m.y, o.y), 0.f);
                m.z = fmaxf(fmaxf(m.z, o.z), 0.f);
                m.w = fmaxf(fmaxf(m.w, o.w), 0.f);
                float4* out4 = (float4*)(out + FEAT_OFF);
                out4[(size_t)(b * NPOINT + q0 + q) * 32 + c4] = m;
            }
        }
    }
}

// ---------------- launch ----------------
extern "C" void kernel_launch(void* const* d_in, const int* in_sizes, int n_in,
                              void* d_out, int out_size)
{
    const float* xyz   = (const float*)d_in[0];
    const float* feat  = (const float*)d_in[1];
    const float* Wm    = (const float*)d_in[2];
    // d_in[3] = bias: cancels inside BatchNorm -> unused
    const float* gamma = (const float*)d_in[4];
    const float* beta  = (const float*)d_in[5];
    float* out = (float*)d_out;

    cudaFuncSetAttribute(mega_kernel, cudaFuncAttributeMaxDynamicSharedMemorySize, SMEM_BYTES);
    zero_kernel<<<1, 128>>>();
    mega_kernel<<<GRID, NT, SMEM_BYTES>>>(xyz, feat, Wm, gamma, beta, out);
}